// round 2
// baseline (speedup 1.0000x reference)
#include <cuda_runtime.h>

#define Bb 4
#define Hh 16
#define Ss 2048
#define Dd 64
#define BH (Bb*Hh)
#define CTX_ELEMS ((size_t)Bb*Hh*Ss*Dd)      // 8388608
#define TILE 64
#define SMS 68   // padded smem stride (multiple of 4 -> float4 aligned, kills bank conflicts)

// ---------------------------------------------------------------------------
// Kernel 1: raw scores  S[bh][q][k] = scale * dot(Q[bh][q], K[bh][k]) + mask[b][k]
// Block: 256 threads computes a 64x64 tile. Each thread: 4q x 4k micro-tile.
// Q,K tiles stored TRANSPOSED in smem ([d][row]) so compute reads are float4
// along the row index (contiguous 256B per 16-thread group -> conflict-free).
// ---------------------------------------------------------------------------
__global__ void sdpa_scores(const float* __restrict__ q,
                            const float* __restrict__ k,
                            const float* __restrict__ mask,
                            float* __restrict__ attn) {
    __shared__ float Qt[TILE][SMS];   // [d][q]
    __shared__ float Kt[TILE][SMS];   // [d][k]

    const int bh = blockIdx.z;
    const int b  = bh / Hh;
    const int q0 = blockIdx.y * TILE;
    const int k0 = blockIdx.x * TILE;
    const float* qb = q + (size_t)bh * Ss * Dd;
    const float* kb = k + (size_t)bh * Ss * Dd;

    const int t  = threadIdx.x;          // 0..255
    const int lr = t >> 4;               // 0..15 (row group for loads)
    const int dc = (t & 15) * 4;         // d-chunk for loads

    #pragma unroll
    for (int p = 0; p < 4; p++) {
        int r = lr + p * 16;
        float4 a = *(const float4*)(qb + (size_t)(q0 + r) * Dd + dc);
        Qt[dc + 0][r] = a.x; Qt[dc + 1][r] = a.y; Qt[dc + 2][r] = a.z; Qt[dc + 3][r] = a.w;
        float4 c = *(const float4*)(kb + (size_t)(k0 + r) * Dd + dc);
        Kt[dc + 0][r] = c.x; Kt[dc + 1][r] = c.y; Kt[dc + 2][r] = c.z; Kt[dc + 3][r] = c.w;
    }
    __syncthreads();

    const int tx = t & 15;               // k micro-tile index
    const int ty = t >> 4;               // q micro-tile index

    float acc[4][4];
    #pragma unroll
    for (int i = 0; i < 4; i++)
        #pragma unroll
        for (int j = 0; j < 4; j++) acc[i][j] = 0.0f;

    #pragma unroll
    for (int d = 0; d < TILE; d++) {
        float4 rq = *(const float4*)&Qt[d][ty * 4];
        float4 rk = *(const float4*)&Kt[d][tx * 4];
        float aq[4] = {rq.x, rq.y, rq.z, rq.w};
        float ak[4] = {rk.x, rk.y, rk.z, rk.w};
        #pragma unroll
        for (int i = 0; i < 4; i++)
            #pragma unroll
            for (int j = 0; j < 4; j++)
                acc[i][j] += aq[i] * ak[j];
    }

    const float scale = 0.125f;          // 1/sqrt(64)
    float4 mv = *(const float4*)(mask + (size_t)b * Ss + k0 + tx * 4);
    float mj[4] = {mv.x, mv.y, mv.z, mv.w};

    #pragma unroll
    for (int i = 0; i < 4; i++) {
        float* orow = attn + ((size_t)bh * Ss + (q0 + ty * 4 + i)) * Ss + k0 + tx * 4;
        float4 o;
        o.x = acc[i][0] * scale + mj[0];
        o.y = acc[i][1] * scale + mj[1];
        o.z = acc[i][2] * scale + mj[2];
        o.w = acc[i][3] * scale + mj[3];
        *(float4*)orow = o;
    }
}

// ---------------------------------------------------------------------------
// Kernel 2: row softmax in place. One block (256 threads) per row of 2048.
// ---------------------------------------------------------------------------
__global__ void sdpa_softmax(float* __restrict__ attn) {
    __shared__ float red[32];
    float* p = attn + (size_t)blockIdx.x * Ss;
    const int t = threadIdx.x;

    float4 v0 = *(const float4*)(p + t * 8);
    float4 v1 = *(const float4*)(p + t * 8 + 4);
    float x[8] = {v0.x, v0.y, v0.z, v0.w, v1.x, v1.y, v1.z, v1.w};

    // block max
    float m = x[0];
    #pragma unroll
    for (int i = 1; i < 8; i++) m = fmaxf(m, x[i]);
    #pragma unroll
    for (int o = 16; o > 0; o >>= 1) m = fmaxf(m, __shfl_xor_sync(0xffffffffu, m, o));
    if ((t & 31) == 0) red[t >> 5] = m;
    __syncthreads();
    if (t < 32) {
        float mm = (t < 8) ? red[t] : -3.4e38f;
        #pragma unroll
        for (int o = 4; o > 0; o >>= 1) mm = fmaxf(mm, __shfl_xor_sync(0xffffffffu, mm, o));
        if (t == 0) red[0] = mm;
    }
    __syncthreads();
    m = red[0];
    __syncthreads();

    // exp + block sum
    float s = 0.0f;
    #pragma unroll
    for (int i = 0; i < 8; i++) { x[i] = __expf(x[i] - m); s += x[i]; }
    #pragma unroll
    for (int o = 16; o > 0; o >>= 1) s += __shfl_xor_sync(0xffffffffu, s, o);
    if ((t & 31) == 0) red[t >> 5] = s;
    __syncthreads();
    if (t < 32) {
        float ss = (t < 8) ? red[t] : 0.0f;
        #pragma unroll
        for (int o = 4; o > 0; o >>= 1) ss += __shfl_xor_sync(0xffffffffu, ss, o);
        if (t == 0) red[0] = ss;
    }
    __syncthreads();
    float inv = 1.0f / red[0];

    float4 o0, o1;
    o0.x = x[0] * inv; o0.y = x[1] * inv; o0.z = x[2] * inv; o0.w = x[3] * inv;
    o1.x = x[4] * inv; o1.y = x[5] * inv; o1.z = x[6] * inv; o1.w = x[7] * inv;
    *(float4*)(p + t * 8)     = o0;
    *(float4*)(p + t * 8 + 4) = o1;
}

// ---------------------------------------------------------------------------
// Kernel 3: context = A @ V.  Block computes 64q x 64d output tile, looping
// over 32 k-tiles. A stored transposed in smem; V row-major (both stride-68).
// ---------------------------------------------------------------------------
__global__ void sdpa_context(const float* __restrict__ attn,
                             const float* __restrict__ v,
                             float* __restrict__ ctx) {
    __shared__ float At[TILE][SMS];   // [k][q]
    __shared__ float Vs[TILE][SMS];   // [k][d]

    const int bh = blockIdx.y;
    const int q0 = blockIdx.x * TILE;
    const float* ab = attn + ((size_t)bh * Ss + q0) * Ss;
    const float* vb = v + (size_t)bh * Ss * Dd;

    const int t  = threadIdx.x;
    const int lr = t >> 4;
    const int dc = (t & 15) * 4;
    const int tx = t & 15;
    const int ty = t >> 4;

    float acc[4][4];
    #pragma unroll
    for (int i = 0; i < 4; i++)
        #pragma unroll
        for (int j = 0; j < 4; j++) acc[i][j] = 0.0f;

    for (int kt = 0; kt < Ss / TILE; kt++) {
        int k0 = kt * TILE;
        #pragma unroll
        for (int p = 0; p < 4; p++) {
            int r = lr + p * 16;
            // A[q0+r][k0+dc..+3] -> At[k][q]
            float4 a = *(const float4*)(ab + (size_t)r * Ss + k0 + dc);
            At[dc + 0][r] = a.x; At[dc + 1][r] = a.y; At[dc + 2][r] = a.z; At[dc + 3][r] = a.w;
            // V[k0+r][dc..+3] -> Vs[r][dc..]
            float4 c = *(const float4*)(vb + (size_t)(k0 + r) * Dd + dc);
            *(float4*)&Vs[r][dc] = c;
        }
        __syncthreads();

        #pragma unroll 8
        for (int kk = 0; kk < TILE; kk++) {
            float4 ra = *(const float4*)&At[kk][ty * 4];
            float4 rv = *(const float4*)&Vs[kk][tx * 4];
            float aa[4] = {ra.x, ra.y, ra.z, ra.w};
            float vv[4] = {rv.x, rv.y, rv.z, rv.w};
            #pragma unroll
            for (int i = 0; i < 4; i++)
                #pragma unroll
                for (int j = 0; j < 4; j++)
                    acc[i][j] += aa[i] * vv[j];
        }
        __syncthreads();
    }

    #pragma unroll
    for (int i = 0; i < 4; i++) {
        float* orow = ctx + ((size_t)bh * Ss + (q0 + ty * 4 + i)) * Dd + tx * 4;
        float4 o = {acc[i][0], acc[i][1], acc[i][2], acc[i][3]};
        *(float4*)orow = o;
    }
}

// ---------------------------------------------------------------------------
extern "C" void kernel_launch(void* const* d_in, const int* in_sizes, int n_in,
                              void* d_out, int out_size) {
    const float* q    = (const float*)d_in[0];
    const float* k    = (const float*)d_in[1];
    const float* v    = (const float*)d_in[2];
    const float* mask = (const float*)d_in[3];

    float* ctx  = (float*)d_out;               // context: B*H*S*D
    float* attn = (float*)d_out + CTX_ELEMS;   // attention: B*H*S*S

    dim3 gA(Ss / TILE, Ss / TILE, BH);         // 32 x 32 x 64
    sdpa_scores<<<gA, 256>>>(q, k, mask, attn);

    sdpa_softmax<<<BH * Ss, 256>>>(attn);      // 131072 rows

    dim3 gC(Ss / TILE, BH);                    // 32 x 64
    sdpa_context<<<gC, 256>>>(attn, v, ctx);
}

// round 4
// speedup vs baseline: 2.4170x; 2.4170x over previous
#include <cuda_runtime.h>
#include <cuda_bf16.h>
#include <cstdint>

#define Bb 4
#define Hh 16
#define Ss 2048
#define Dd 64
#define BH (Bb*Hh)
#define CTX_ELEMS ((size_t)Bb*Hh*Ss*Dd)      // 8388608

// ---------------------------------------------------------------------------
// Scratch (allocation-free rule: __device__ globals)
// ---------------------------------------------------------------------------
__device__ __nv_bfloat16 g_Qhi[(size_t)BH*Ss*Dd];
__device__ __nv_bfloat16 g_Qlo[(size_t)BH*Ss*Dd];
__device__ __nv_bfloat16 g_Khi[(size_t)BH*Ss*Dd];
__device__ __nv_bfloat16 g_Klo[(size_t)BH*Ss*Dd];
__device__ __nv_bfloat16 g_Vthi[(size_t)BH*Dd*Ss];   // [bh][d][k]
__device__ __nv_bfloat16 g_Vtlo[(size_t)BH*Dd*Ss];

// ---------------------------------------------------------------------------
// Helpers
// ---------------------------------------------------------------------------
__device__ __forceinline__ uint32_t smem_u32(const void* p) {
    uint32_t a;
    asm("{ .reg .u64 t; cvta.to.shared.u64 t, %1; cvt.u32.u64 %0, t; }" : "=r"(a) : "l"(p));
    return a;
}
__device__ __forceinline__ uint32_t pack2(float a, float b) {
    __nv_bfloat162 t;
    t.x = __float2bfloat16(a);
    t.y = __float2bfloat16(b);
    return *(uint32_t*)&t;
}
// swizzled smem address: 128B rows, XOR bits[6:4] with row&7
__device__ __forceinline__ uint32_t sw_addr(uint32_t base, int row, int kbyte) {
    return base + row * 128 + (kbyte ^ ((row & 7) << 4));
}
__device__ __forceinline__ void ldsm4(uint32_t r[4], uint32_t addr) {
    asm volatile("ldmatrix.sync.aligned.m8n8.x4.shared.b16 {%0,%1,%2,%3}, [%4];"
        : "=r"(r[0]), "=r"(r[1]), "=r"(r[2]), "=r"(r[3]) : "r"(addr));
}
__device__ __forceinline__ void mma16816(float c[4], const uint32_t a[4], const uint32_t b[2]) {
    asm volatile("mma.sync.aligned.m16n8k16.row.col.f32.bf16.bf16.f32 "
        "{%0,%1,%2,%3}, {%4,%5,%6,%7}, {%8,%9}, {%0,%1,%2,%3};"
        : "+f"(c[0]), "+f"(c[1]), "+f"(c[2]), "+f"(c[3])
        : "r"(a[0]), "r"(a[1]), "r"(a[2]), "r"(a[3]), "r"(b[0]), "r"(b[1]));
}

// ---------------------------------------------------------------------------
// Prep 1: fp32 -> (hi, lo) bf16 split, same layout.
// ---------------------------------------------------------------------------
__global__ void conv_split(const float* __restrict__ src,
                           __nv_bfloat16* __restrict__ hi,
                           __nv_bfloat16* __restrict__ lo) {
    size_t i = ((size_t)blockIdx.x * blockDim.x + threadIdx.x) * 4;
    float4 v = *(const float4*)(src + i);
    float f[4] = {v.x, v.y, v.z, v.w};
    float r[4];
    __nv_bfloat16 hb[4];
    #pragma unroll
    for (int j = 0; j < 4; j++) { hb[j] = __float2bfloat16(f[j]); r[j] = f[j] - __bfloat162float(hb[j]); }
    uint32_t h0 = pack2(__bfloat162float(hb[0]), __bfloat162float(hb[1]));
    uint32_t h1 = pack2(__bfloat162float(hb[2]), __bfloat162float(hb[3]));
    uint32_t l0 = pack2(r[0], r[1]);
    uint32_t l1 = pack2(r[2], r[3]);
    *(uint2*)(hi + i) = make_uint2(h0, h1);
    *(uint2*)(lo + i) = make_uint2(l0, l1);
}

// ---------------------------------------------------------------------------
// Prep 2: V [bh][k][d] fp32 -> Vt hi/lo [bh][d][k] bf16.
// ---------------------------------------------------------------------------
__global__ void transpose_v(const float* __restrict__ v) {
    __shared__ float Vs[64][68];
    const int bh = blockIdx.y;
    const int k0 = blockIdx.x * 64;
    const int t = threadIdx.x;     // 256

    #pragma unroll
    for (int p = 0; p < 4; p++) {
        int lin = t + 256 * p;       // 1024 float4 = 64x64
        int r = lin >> 4, g4 = lin & 15;
        float4 a = *(const float4*)(v + ((size_t)bh * Ss + k0 + r) * Dd + g4 * 4);
        Vs[r][g4 * 4 + 0] = a.x; Vs[r][g4 * 4 + 1] = a.y;
        Vs[r][g4 * 4 + 2] = a.z; Vs[r][g4 * 4 + 3] = a.w;
    }
    __syncthreads();

    #pragma unroll
    for (int p = 0; p < 2; p++) {
        int lin = t + 256 * p;       // 512 uint4 = 64 d x 8 kgroups
        int d = lin >> 3, kg = lin & 7;
        uint32_t hw[4], lw[4];
        #pragma unroll
        for (int j = 0; j < 4; j++) {
            float a = Vs[kg * 8 + j * 2][d];
            float b = Vs[kg * 8 + j * 2 + 1][d];
            __nv_bfloat16 ha = __float2bfloat16(a), hb = __float2bfloat16(b);
            hw[j] = pack2(__bfloat162float(ha), __bfloat162float(hb));
            lw[j] = pack2(a - __bfloat162float(ha), b - __bfloat162float(hb));
        }
        size_t o = ((size_t)bh * Dd + d) * Ss + k0 + kg * 8;
        *(uint4*)(g_Vthi + o) = make_uint4(hw[0], hw[1], hw[2], hw[3]);
        *(uint4*)(g_Vtlo + o) = make_uint4(lw[0], lw[1], lw[2], lw[3]);
    }
}

// ---------------------------------------------------------------------------
// Kernel 1: scores via mma.sync.  Block 256 thr = 8 warps, tile 128q x 128k.
// Warp tile 32x64: 2 m-frags x 8 n-frags. bf16x3: QhKh + QhKl + QlKh.
// ---------------------------------------------------------------------------
#define SC_OFF_MASK  0
#define SC_OFF_QHI   512
#define SC_OFF_QLO   (SC_OFF_QHI + 16384)
#define SC_OFF_KHI   (SC_OFF_QLO + 16384)
#define SC_OFF_KLO   (SC_OFF_KHI + 16384)
#define SC_SMEM      (SC_OFF_KLO + 16384)     // 66048

__global__ void __launch_bounds__(256)
sdpa_scores_mma(const float* __restrict__ mask, float* __restrict__ attn) {
    extern __shared__ char smem[];
    const uint32_t sb = smem_u32(smem);
    const int t = threadIdx.x, lane = t & 31, w = t >> 5;
    const int bh = blockIdx.z, b = bh / Hh;
    const int q0 = blockIdx.y * 128, k0 = blockIdx.x * 128;

    // ---- stage 4 bf16 tiles (128 rows x 128B) swizzled ----
    const __nv_bfloat16* srcs[4] = {
        g_Qhi + (size_t)(bh * Ss + q0) * Dd, g_Qlo + (size_t)(bh * Ss + q0) * Dd,
        g_Khi + (size_t)(bh * Ss + k0) * Dd, g_Klo + (size_t)(bh * Ss + k0) * Dd };
    const uint32_t offs[4] = {SC_OFF_QHI, SC_OFF_QLO, SC_OFF_KHI, SC_OFF_KLO};
    #pragma unroll
    for (int tile = 0; tile < 4; tile++) {
        const char* src = (const char*)srcs[tile];
        #pragma unroll
        for (int p = 0; p < 4; p++) {
            int g = t + 256 * p;           // 1024 granules of 16B
            int r = g >> 3, x = (g & 7) * 16;
            uint4 d = *(const uint4*)(src + r * 128 + x);
            *(uint4*)(smem + offs[tile] + r * 128 + (x ^ ((r & 7) << 4))) = d;
        }
    }
    if (t < 32) *(float4*)(smem + SC_OFF_MASK + t * 16) =
        *(const float4*)(mask + (size_t)b * Ss + k0 + t * 4);
    __syncthreads();

    const int wm = w >> 1, wn = w & 1;
    const int m_base = wm * 32, n_base = wn * 64;
    const uint32_t qh = sb + SC_OFF_QHI, ql = sb + SC_OFF_QLO;
    const uint32_t kh = sb + SC_OFF_KHI, kl = sb + SC_OFF_KLO;

    float c[2][8][4];
    #pragma unroll
    for (int i = 0; i < 2; i++)
        #pragma unroll
        for (int j = 0; j < 8; j++)
            #pragma unroll
            for (int e = 0; e < 4; e++) c[i][j][e] = 0.0f;

    #pragma unroll
    for (int ks = 0; ks < 4; ks++) {
        const int ko = ks * 16;
        // A fragments (hi & lo)
        uint32_t AH[2][4], AL[2][4];
        #pragma unroll
        for (int mf = 0; mf < 2; mf++) {
            int row = m_base + mf * 16 + (lane & 15);
            int kb = (ko + ((lane >> 4) << 3)) * 2;
            ldsm4(AH[mf], sw_addr(qh, row, kb));
            ldsm4(AL[mf], sw_addr(ql, row, kb));
        }
        // B in pairs of n-frags to bound live registers
        #pragma unroll
        for (int np = 0; np < 4; np++) {
            int row = n_base + np * 16 + (lane & 7) + ((lane >> 4) << 3);
            int kb = (ko + (((lane >> 3) & 1) << 3)) * 2;
            uint32_t BH4[4], BL4[4];
            ldsm4(BH4, sw_addr(kh, row, kb));
            ldsm4(BL4, sw_addr(kl, row, kb));
            #pragma unroll
            for (int h = 0; h < 2; h++) {
                const uint32_t bhr[2] = {BH4[2 * h], BH4[2 * h + 1]};
                const uint32_t blr[2] = {BL4[2 * h], BL4[2 * h + 1]};
                #pragma unroll
                for (int mf = 0; mf < 2; mf++) {
                    mma16816(c[mf][2 * np + h], AH[mf], bhr);
                    mma16816(c[mf][2 * np + h], AH[mf], blr);
                    mma16816(c[mf][2 * np + h], AL[mf], bhr);
                }
            }
        }
    }

    // ---- epilogue: scale + mask, write fp32 attn ----
    const float* mrow = (const float*)(smem + SC_OFF_MASK);
    #pragma unroll
    for (int mf = 0; mf < 2; mf++) {
        int r0 = q0 + m_base + mf * 16 + (lane >> 2);
        #pragma unroll
        for (int nf = 0; nf < 8; nf++) {
            int col = n_base + nf * 8 + 2 * (lane & 3);
            float m0 = mrow[col], m1 = mrow[col + 1];
            float2 v0 = {c[mf][nf][0] * 0.125f + m0, c[mf][nf][1] * 0.125f + m1};
            float2 v1 = {c[mf][nf][2] * 0.125f + m0, c[mf][nf][3] * 0.125f + m1};
            *(float2*)(attn + ((size_t)bh * Ss + r0) * Ss + k0 + col) = v0;
            *(float2*)(attn + ((size_t)bh * Ss + r0 + 8) * Ss + k0 + col) = v1;
        }
    }
}

// ---------------------------------------------------------------------------
// Kernel 2: row softmax in place.
// ---------------------------------------------------------------------------
__global__ void sdpa_softmax(float* __restrict__ attn) {
    __shared__ float red[32];
    float* p = attn + (size_t)blockIdx.x * Ss;
    const int t = threadIdx.x;

    float4 v0 = *(const float4*)(p + t * 8);
    float4 v1 = *(const float4*)(p + t * 8 + 4);
    float x[8] = {v0.x, v0.y, v0.z, v0.w, v1.x, v1.y, v1.z, v1.w};

    float m = x[0];
    #pragma unroll
    for (int i = 1; i < 8; i++) m = fmaxf(m, x[i]);
    #pragma unroll
    for (int o = 16; o > 0; o >>= 1) m = fmaxf(m, __shfl_xor_sync(0xffffffffu, m, o));
    if ((t & 31) == 0) red[t >> 5] = m;
    __syncthreads();
    if (t < 32) {
        float mm = (t < 8) ? red[t] : -3.4e38f;
        #pragma unroll
        for (int o = 4; o > 0; o >>= 1) mm = fmaxf(mm, __shfl_xor_sync(0xffffffffu, mm, o));
        if (t == 0) red[0] = mm;
    }
    __syncthreads();
    m = red[0];
    __syncthreads();

    float s = 0.0f;
    #pragma unroll
    for (int i = 0; i < 8; i++) { x[i] = __expf(x[i] - m); s += x[i]; }
    #pragma unroll
    for (int o = 16; o > 0; o >>= 1) s += __shfl_xor_sync(0xffffffffu, s, o);
    if ((t & 31) == 0) red[t >> 5] = s;
    __syncthreads();
    if (t < 32) {
        float ss = (t < 8) ? red[t] : 0.0f;
        #pragma unroll
        for (int o = 4; o > 0; o >>= 1) ss += __shfl_xor_sync(0xffffffffu, ss, o);
        if (t == 0) red[0] = ss;
    }
    __syncthreads();
    float inv = 1.0f / red[0];

    float4 o0, o1;
    o0.x = x[0] * inv; o0.y = x[1] * inv; o0.z = x[2] * inv; o0.w = x[3] * inv;
    o1.x = x[4] * inv; o1.y = x[5] * inv; o1.z = x[6] * inv; o1.w = x[7] * inv;
    *(float4*)(p + t * 8)     = o0;
    *(float4*)(p + t * 8 + 4) = o1;
}

// ---------------------------------------------------------------------------
// Kernel 3: context via mma.sync.  Block 256 thr, tile 128q x 64d, 32 chunks
// of K=64. A (attn) converted fp32->bf16 hi/lo in-kernel. Warp tile 32x32.
// ---------------------------------------------------------------------------
#define CT_OFF_AHI  0
#define CT_OFF_ALO  (CT_OFF_AHI + 16384)
#define CT_OFF_VHI  (CT_OFF_ALO + 16384)
#define CT_OFF_VLO  (CT_OFF_VHI + 8192)
#define CT_SMEM     (CT_OFF_VLO + 8192)       // 49152

__global__ void __launch_bounds__(256)
sdpa_context_mma(const float* __restrict__ attn, float* __restrict__ ctx) {
    extern __shared__ char smem[];
    const uint32_t sb = smem_u32(smem);
    const int t = threadIdx.x, lane = t & 31, w = t >> 5;
    const int bh = blockIdx.y;
    const int q0 = blockIdx.x * 128;

    const float* ab = attn + ((size_t)bh * Ss + q0) * Ss;
    const char* vhb = (const char*)(g_Vthi + (size_t)bh * Dd * Ss);
    const char* vlb = (const char*)(g_Vtlo + (size_t)bh * Dd * Ss);

    const int wm = w >> 1, wn = w & 1;
    const int m_base = wm * 32, n_base = wn * 32;
    const uint32_t ah = sb + CT_OFF_AHI, al = sb + CT_OFF_ALO;
    const uint32_t vh = sb + CT_OFF_VHI, vl = sb + CT_OFF_VLO;

    float c[2][4][4];
    #pragma unroll
    for (int i = 0; i < 2; i++)
        #pragma unroll
        for (int j = 0; j < 4; j++)
            #pragma unroll
            for (int e = 0; e < 4; e++) c[i][j][e] = 0.0f;

    for (int ch = 0; ch < 32; ch++) {
        if (ch) __syncthreads();    // previous chunk's ldsm done before overwrite

        // A chunk: 128 rows x 64 fp32 -> bf16 hi/lo, swizzled
        #pragma unroll
        for (int p = 0; p < 8; p++) {
            int lin = t + 256 * p;            // 2048 float4
            int r = lin >> 4, g4 = lin & 15;
            float4 a = *(const float4*)(ab + (size_t)r * Ss + ch * 64 + g4 * 4);
            __nv_bfloat16 h0 = __float2bfloat16(a.x), h1 = __float2bfloat16(a.y);
            __nv_bfloat16 h2 = __float2bfloat16(a.z), h3 = __float2bfloat16(a.w);
            uint32_t hi0 = pack2(__bfloat162float(h0), __bfloat162float(h1));
            uint32_t hi1 = pack2(__bfloat162float(h2), __bfloat162float(h3));
            uint32_t lo0 = pack2(a.x - __bfloat162float(h0), a.y - __bfloat162float(h1));
            uint32_t lo1 = pack2(a.z - __bfloat162float(h2), a.w - __bfloat162float(h3));
            int x = g4 * 8;
            uint32_t swo = r * 128 + (x ^ ((r & 7) << 4));
            *(uint2*)(smem + CT_OFF_AHI + swo) = make_uint2(hi0, hi1);
            *(uint2*)(smem + CT_OFF_ALO + swo) = make_uint2(lo0, lo1);
        }
        // V chunk: 64 d-rows x 64 k bf16 hi/lo
        #pragma unroll
        for (int p = 0; p < 2; p++) {
            int g = t + 256 * p;              // 512 granules of 16B
            int r = g >> 3, x = (g & 7) * 16;
            uint4 dh = *(const uint4*)(vhb + (size_t)r * (Ss * 2) + ch * 128 + x);
            uint4 dl = *(const uint4*)(vlb + (size_t)r * (Ss * 2) + ch * 128 + x);
            uint32_t swo = r * 128 + (x ^ ((r & 7) << 4));
            *(uint4*)(smem + CT_OFF_VHI + swo) = dh;
            *(uint4*)(smem + CT_OFF_VLO + swo) = dl;
        }
        __syncthreads();

        #pragma unroll
        for (int ks = 0; ks < 4; ks++) {
            const int ko = ks * 16;
            uint32_t AH[2][4], AL[2][4];
            #pragma unroll
            for (int mf = 0; mf < 2; mf++) {
                int row = m_base + mf * 16 + (lane & 15);
                int kb = (ko + ((lane >> 4) << 3)) * 2;
                ldsm4(AH[mf], sw_addr(ah, row, kb));
                ldsm4(AL[mf], sw_addr(al, row, kb));
            }
            #pragma unroll
            for (int np = 0; np < 2; np++) {
                int row = n_base + np * 16 + (lane & 7) + ((lane >> 4) << 3);
                int kb = (ko + (((lane >> 3) & 1) << 3)) * 2;
                uint32_t BH4[4], BL4[4];
                ldsm4(BH4, sw_addr(vh, row, kb));
                ldsm4(BL4, sw_addr(vl, row, kb));
                #pragma unroll
                for (int h = 0; h < 2; h++) {
                    const uint32_t bhr[2] = {BH4[2 * h], BH4[2 * h + 1]};
                    const uint32_t blr[2] = {BL4[2 * h], BL4[2 * h + 1]};
                    #pragma unroll
                    for (int mf = 0; mf < 2; mf++) {
                        mma16816(c[mf][2 * np + h], AH[mf], bhr);
                        mma16816(c[mf][2 * np + h], AH[mf], blr);
                        mma16816(c[mf][2 * np + h], AL[mf], bhr);
                    }
                }
            }
        }
    }

    // ---- epilogue ----
    #pragma unroll
    for (int mf = 0; mf < 2; mf++) {
        int r0 = q0 + m_base + mf * 16 + (lane >> 2);
        #pragma unroll
        for (int nf = 0; nf < 4; nf++) {
            int col = n_base + nf * 8 + 2 * (lane & 3);
            float2 v0 = {c[mf][nf][0], c[mf][nf][1]};
            float2 v1 = {c[mf][nf][2], c[mf][nf][3]};
            *(float2*)(ctx + ((size_t)bh * Ss + r0) * Dd + col) = v0;
            *(float2*)(ctx + ((size_t)bh * Ss + r0 + 8) * Dd + col) = v1;
        }
    }
}

// ---------------------------------------------------------------------------
extern "C" void kernel_launch(void* const* d_in, const int* in_sizes, int n_in,
                              void* d_out, int out_size) {
    const float* q    = (const float*)d_in[0];
    const float* k    = (const float*)d_in[1];
    const float* v    = (const float*)d_in[2];
    const float* mask = (const float*)d_in[3];

    float* ctx  = (float*)d_out;
    float* attn = (float*)d_out + CTX_ELEMS;

    cudaFuncSetAttribute(sdpa_scores_mma,  cudaFuncAttributeMaxDynamicSharedMemorySize, SC_SMEM);
    cudaFuncSetAttribute(sdpa_context_mma, cudaFuncAttributeMaxDynamicSharedMemorySize, CT_SMEM);

    __nv_bfloat16 *qhi, *qlo, *khi, *klo;
    cudaGetSymbolAddress((void**)&qhi, g_Qhi);
    cudaGetSymbolAddress((void**)&qlo, g_Qlo);
    cudaGetSymbolAddress((void**)&khi, g_Khi);
    cudaGetSymbolAddress((void**)&klo, g_Klo);

    const size_t nf4 = (size_t)BH * Ss * Dd / 4;   // 2097152
    conv_split<<<nf4 / 256, 256>>>(q, qhi, qlo);
    conv_split<<<nf4 / 256, 256>>>(k, khi, klo);
    transpose_v<<<dim3(Ss / 64, BH), 256>>>(v);

    sdpa_scores_mma<<<dim3(Ss / 128, Ss / 128, BH), 256, SC_SMEM>>>(mask, attn);
    sdpa_softmax<<<BH * Ss, 256>>>(attn);
    sdpa_context_mma<<<dim3(Ss / 128, BH), 256, CT_SMEM>>>(attn, ctx);
}